// round 1
// baseline (speedup 1.0000x reference)
#include <cuda_runtime.h>
#include <cuda_bf16.h>
#include <math.h>

// ---------------- problem constants ----------------
#define BB 2
#define HEADS 8
#define DH 32
#define ADIM 256
#define NKTOT 2240          // 1024 + 960 + 256
#define NQTOT 1600          // 1024 + 576
#define KPD 1024            // 8*8*16
#define VPD 2048            // 8*8*32
#define QPD 1024
#define VHD 256             // VPD / HEADS

// ---------------- scratch buffers (static device allocs) ----------------
__device__ float g_kseq[BB*NKTOT*KPD];          // 4,587,520
__device__ float g_vseq[BB*NKTOT*VPD];          // 9,175,040
__device__ float g_qseq[BB*NQTOT*QPD];          // 3,276,800
__device__ float g_khid[BB*NKTOT*ADIM];
__device__ float g_kemb[BB*NKTOT*ADIM];
__device__ float g_qhid[BB*NQTOT*ADIM];
__device__ float g_qemb[BB*NQTOT*ADIM];
__device__ float g_scores[(size_t)BB*HEADS*NQTOT*NKTOT];      // 57,344,000
__device__ float g_weighted[(size_t)BB*3*HEADS*NQTOT*VHD];    // 19,660,800
__device__ float g_x0[BB*96*256*256];           // 12,582,912
__device__ float g_x1[BB*96*192*192];           // 7,077,888
__device__ float g_hid1[(size_t)BB*384*256*256];// 50,331,648
__device__ float g_hid2[(size_t)BB*384*256*256];

__device__ __forceinline__ float gelu_f(float x){
    return 0.5f*x*(1.0f + tanhf(0.7978845608028654f*(x + 0.044715f*x*x*x)));
}

// ---------------- patchify: NCHW image -> [b, n, (ph,pw,c)] ----------------
__global__ void k_patchify(const float* __restrict__ src, float* __restrict__ dst,
                           int C, int Himg, int Wimg, int nOff, int Ntot, int featDim, int total)
{
    int idx = blockIdx.x*blockDim.x + threadIdx.x;
    if (idx >= total) return;
    int x = idx % Wimg;
    int t = idx / Wimg;
    int y = t % Himg; t /= Himg;
    int c = t % C;    int b = t / C;
    int hp = y>>3, ph = y&7, wp = x>>3, pw = x&7;
    int n = hp*(Wimg>>3) + wp;
    int f = ((ph<<3)+pw)*C + c;
    dst[(size_t)(b*Ntot + nOff + n)*featDim + f] = src[idx];
}

// ---------------- layernorm rows (in place) ----------------
__global__ void k_layernorm(float* __restrict__ v, const float* __restrict__ g,
                            const float* __restrict__ bta, int dim)
{
    float* p = v + (size_t)blockIdx.x*dim;
    __shared__ float red[256];
    int tid = threadIdx.x;
    float s=0.f, s2=0.f;
    for (int i=tid;i<dim;i+=256){ float x=p[i]; s+=x; s2+=x*x; }
    red[tid]=s; __syncthreads();
    for (int o=128;o>0;o>>=1){ if(tid<o) red[tid]+=red[tid+o]; __syncthreads(); }
    float mean = red[0]/dim; __syncthreads();
    red[tid]=s2; __syncthreads();
    for (int o=128;o>0;o>>=1){ if(tid<o) red[tid]+=red[tid+o]; __syncthreads(); }
    float var = red[0]/dim - mean*mean;
    float rstd = rsqrtf(var + 1e-5f);
    for (int i=tid;i<dim;i+=256){ float x=p[i]; p[i]=(x-mean)*rstd*g[i]+bta[i]; }
}

// ---------------- generic tiled GEMM body: C = act(A@B + bias) ----------------
// BM=BN=64, BK=16, 256 threads, 4x4 per thread. Requires M%64==0, N%64==0, K%16==0.
__device__ __forceinline__ void gemm_body(
    const float* __restrict__ A, int lda,
    const float* __restrict__ Bm, int ldb,
    const float* __restrict__ bias,
    float* __restrict__ C, int ldc,
    int K, int act, int bm, int bn)
{
    __shared__ float As[16][65];
    __shared__ float Bs[16][65];
    int tid = threadIdx.x;
    int tx = tid & 15, ty = tid >> 4;
    int ra = tid>>2, ca=(tid&3)<<2;
    int rb = tid>>4, cb=(tid&15)<<2;
    float acc[4][4];
    #pragma unroll
    for(int i=0;i<4;i++)
        #pragma unroll
        for(int j=0;j<4;j++) acc[i][j]=0.f;

    for (int k0=0;k0<K;k0+=16){
        float4 av = *(const float4*)(A + (size_t)(bm+ra)*lda + k0 + ca);
        As[ca  ][ra]=av.x; As[ca+1][ra]=av.y; As[ca+2][ra]=av.z; As[ca+3][ra]=av.w;
        float4 bv = *(const float4*)(Bm + (size_t)(k0+rb)*ldb + bn + cb);
        Bs[rb][cb  ]=bv.x; Bs[rb][cb+1]=bv.y; Bs[rb][cb+2]=bv.z; Bs[rb][cb+3]=bv.w;
        __syncthreads();
        #pragma unroll
        for(int kk=0;kk<16;kk++){
            float a[4], b[4];
            #pragma unroll
            for(int i=0;i<4;i++) a[i]=As[kk][(ty<<2)+i];
            #pragma unroll
            for(int j=0;j<4;j++) b[j]=Bs[kk][(tx<<2)+j];
            #pragma unroll
            for(int i=0;i<4;i++)
                #pragma unroll
                for(int j=0;j<4;j++) acc[i][j] += a[i]*b[j];
        }
        __syncthreads();
    }
    #pragma unroll
    for(int i=0;i<4;i++){
        #pragma unroll
        for(int j=0;j<4;j++){
            float v2 = acc[i][j];
            if (bias) v2 += bias[bn + (tx<<2) + j];
            if (act==1) v2 = gelu_f(v2);
            C[(size_t)(bm + (ty<<2) + i)*ldc + bn + (tx<<2) + j] = v2;
        }
    }
}

__global__ void k_gemm(const float* __restrict__ A, int lda,
                       const float* __restrict__ Bm, int ldb,
                       const float* __restrict__ bias,
                       float* __restrict__ C, int ldc, int K, int act)
{
    gemm_body(A, lda, Bm, ldb, bias, C, ldc, K, act, blockIdx.y<<6, blockIdx.x<<6);
}

// ---------------- A*V per (b, seg, head) ----------------
__global__ void k_av()
{
    int z = blockIdx.z;
    int h = z & 7; int t = z >> 3; int seg = t % 3; int b = t / 3;
    const int segOff[3] = {0, 1024, 1984};
    const int segN[3]   = {1024, 960, 256};
    const float* A = g_scores + (size_t)(b*HEADS + h)*NQTOT*NKTOT + segOff[seg];
    const float* Bv = g_vseq + ((size_t)b*NKTOT + segOff[seg])*VPD + h*VHD;
    float* C = g_weighted + (size_t)((b*3 + seg)*HEADS + h)*NQTOT*VHD;
    gemm_body(A, NKTOT, Bv, VPD, nullptr, C, VHD, segN[seg], 0, blockIdx.y<<6, blockIdx.x<<6);
}

// ---------------- Q @ K^T (d=32) ----------------
__global__ void k_qk()
{
    __shared__ float Qs[64][33];
    __shared__ float Ks[64][33];
    int z = blockIdx.z; int b = z>>3, h = z&7;
    const float* Qb = g_qemb + (size_t)b*NQTOT*ADIM + h*DH;
    const float* Kb = g_kemb + (size_t)b*NKTOT*ADIM + h*DH;
    float* Sb = g_scores + (size_t)z*NQTOT*NKTOT;
    int tid = threadIdx.x;
    int bm = blockIdx.y<<6, bn = blockIdx.x<<6;
    int r = tid>>2, c = (tid&3)<<3;
    {
        float4 q0 = *(const float4*)(Qb + (size_t)(bm+r)*ADIM + c);
        float4 q1 = *(const float4*)(Qb + (size_t)(bm+r)*ADIM + c + 4);
        Qs[r][c  ]=q0.x; Qs[r][c+1]=q0.y; Qs[r][c+2]=q0.z; Qs[r][c+3]=q0.w;
        Qs[r][c+4]=q1.x; Qs[r][c+5]=q1.y; Qs[r][c+6]=q1.z; Qs[r][c+7]=q1.w;
        float4 k0v = *(const float4*)(Kb + (size_t)(bn+r)*ADIM + c);
        float4 k1v = *(const float4*)(Kb + (size_t)(bn+r)*ADIM + c + 4);
        Ks[r][c  ]=k0v.x; Ks[r][c+1]=k0v.y; Ks[r][c+2]=k0v.z; Ks[r][c+3]=k0v.w;
        Ks[r][c+4]=k1v.x; Ks[r][c+5]=k1v.y; Ks[r][c+6]=k1v.z; Ks[r][c+7]=k1v.w;
    }
    __syncthreads();
    int tx = tid&15, ty = tid>>4;
    float acc[4][4];
    #pragma unroll
    for(int i=0;i<4;i++)
        #pragma unroll
        for(int j=0;j<4;j++) acc[i][j]=0.f;
    #pragma unroll
    for(int kk=0;kk<32;kk++){
        float a[4], bq[4];
        #pragma unroll
        for(int i=0;i<4;i++) a[i]=Qs[(ty<<2)+i][kk];
        #pragma unroll
        for(int j=0;j<4;j++) bq[j]=Ks[(tx<<2)+j][kk];
        #pragma unroll
        for(int i=0;i<4;i++)
            #pragma unroll
            for(int j=0;j<4;j++) acc[i][j] += a[i]*bq[j];
    }
    const float scale = 0.17677669529663689f; // 1/sqrt(32)
    #pragma unroll
    for(int i=0;i<4;i++)
        #pragma unroll
        for(int j=0;j<4;j++)
            Sb[(size_t)(bm+(ty<<2)+i)*NKTOT + bn + (tx<<2) + j] = acc[i][j]*scale;
}

// ---------------- row softmax over 2240 keys ----------------
__global__ void k_softmax()
{
    __shared__ float buf[NKTOT];
    __shared__ float red[256];
    float* p = g_scores + (size_t)blockIdx.x*NKTOT;
    int tid = threadIdx.x;
    float m = -1e30f;
    for (int i=tid;i<NKTOT;i+=256){ float x=p[i]; buf[i]=x; m=fmaxf(m,x); }
    red[tid]=m; __syncthreads();
    for (int o=128;o>0;o>>=1){ if(tid<o) red[tid]=fmaxf(red[tid],red[tid+o]); __syncthreads(); }
    m = red[0]; __syncthreads();
    float s = 0.f;
    for (int i=tid;i<NKTOT;i+=256){ float e=__expf(buf[i]-m); buf[i]=e; s+=e; }
    red[tid]=s; __syncthreads();
    for (int o=128;o>0;o>>=1){ if(tid<o) red[tid]+=red[tid+o]; __syncthreads(); }
    float inv = 1.0f/red[0];
    for (int i=tid;i<NKTOT;i+=256) p[i]=buf[i]*inv;
}

// ---------------- gather weighted -> NCHW 96-channel image ----------------
__global__ void k_assemble(const float* __restrict__ W, float* __restrict__ X,
                           int qh, int qw, int qoff, int total)
{
    int idx = blockIdx.x*blockDim.x + threadIdx.x;
    if (idx >= total) return;
    int x = idx % qw;
    int t = idx / qw;
    int y = t % qh; t /= qh;
    int ch = t % 96; int b = t / 96;
    int hd = ch/12; int r2 = ch%12; int seg = r2>>2; int c = r2&3;
    int py=y>>3, ph=y&7, px=x>>3, pw=x&7;
    int n = qoff + py*(qw>>3) + px;
    int d = ((ph<<3)+pw)*4 + c;
    X[idx] = W[ ((size_t)((b*3+seg)*HEADS + hd)*NQTOT + n)*VHD + d ];
}

// ---------------- mbconv expand: grouped 1x1 (96->384, groups 8) + gelu ----------------
__global__ void k_expand(const float* __restrict__ X, const float* __restrict__ w,
                         const float* __restrict__ bias, float* __restrict__ H, int npix)
{
    __shared__ float ws[384*12];
    __shared__ float bs[384];
    int tid = threadIdx.x;
    for (int i=tid;i<4608;i+=256) ws[i]=w[i];
    for (int i=tid;i<384;i+=256) bs[i]=bias[i];
    __syncthreads();
    int pix = blockIdx.x*32 + (tid&31);
    int g = tid>>5;
    int b = blockIdx.y;
    const float* xin = X + ((size_t)b*96 + g*12)*npix + pix;
    float iv[12];
    #pragma unroll
    for (int i=0;i<12;i++) iv[i]=xin[(size_t)i*npix];
    float* hout = H + ((size_t)b*384 + g*48)*npix + pix;
    #pragma unroll 4
    for (int o=0;o<48;o++){
        const float* wr = &ws[(g*48+o)*12];
        float s2 = 0.f;
        #pragma unroll
        for (int i=0;i<12;i++) s2 += iv[i]*wr[i];
        hout[(size_t)o*npix] = gelu_f(s2 + bs[g*48+o]);
    }
}

// ---------------- depthwise 7x7 SAME + gelu ----------------
__global__ void k_dw(const float* __restrict__ H, const float* __restrict__ w,
                     const float* __restrict__ bias, float* __restrict__ O, int Hh, int Ww)
{
    __shared__ float sm[14][39];
    __shared__ float ws[49];
    int bz = blockIdx.z; int ch = bz % 384; int b = bz / 384;
    const float* in = H + ((size_t)(b*384)+ch)*Hh*Ww;
    int tx = threadIdx.x, ty = threadIdx.y; int tid = ty*32+tx;
    if (tid < 49) ws[tid] = w[ch*49 + tid];
    int bx = blockIdx.x*32, by = blockIdx.y*8;
    for (int i=tid;i<14*38;i+=256){
        int ly=i/38, lx=i%38;
        int gy=by+ly-3, gx=bx+lx-3;
        sm[ly][lx] = (gy>=0 && gy<Hh && gx>=0 && gx<Ww) ? in[(size_t)gy*Ww+gx] : 0.f;
    }
    __syncthreads();
    float s2 = 0.f;
    #pragma unroll
    for (int ky=0;ky<7;ky++)
        #pragma unroll
        for (int kx=0;kx<7;kx++)
            s2 += sm[ty+ky][tx+kx]*ws[ky*7+kx];
    O[((size_t)(b*384)+ch)*Hh*Ww + (size_t)(by+ty)*Ww + bx+tx] = gelu_f(s2 + bias[ch]);
}

// ---------------- mbconv proj: grouped 1x1 (384->32, groups 8) ----------------
__global__ void k_proj(const float* __restrict__ H, const float* __restrict__ w,
                       const float* __restrict__ bias, float* __restrict__ O, int npix)
{
    __shared__ float ws[32*48];
    int tid = threadIdx.x;
    for (int i=tid;i<1536;i+=256) ws[i]=w[i];
    __syncthreads();
    int pix = blockIdx.x*32 + (tid&31);
    int g = tid>>5;
    int b = blockIdx.y;
    const float* hin = H + ((size_t)b*384 + g*48)*npix + pix;
    float iv[48];
    #pragma unroll
    for (int i=0;i<48;i++) iv[i]=hin[(size_t)i*npix];
    #pragma unroll
    for (int o=0;o<4;o++){
        int oc = g*4 + o;
        const float* wr = &ws[oc*48];
        float s2 = 0.f;
        #pragma unroll
        for (int i=0;i<48;i++) s2 += iv[i]*wr[i];
        O[((size_t)b*32 + oc)*npix + pix] = s2 + bias[oc];
    }
}

// ---------------- host launch ----------------
#define GETSYM(p, sym) do { cudaGetSymbolAddress((void**)&(p), sym); } while(0)

extern "C" void kernel_launch(void* const* d_in, const int* in_sizes, int n_in,
                              void* d_out, int out_size)
{
    // Disambiguate input ordering: dict order has values_0 (4194304) at index 1,
    // signature order has keys_1 (1966080) there.
    bool dictOrder = (in_sizes[1] == 4194304);
    const float* K0 = (const float*)d_in[0];
    const float* V0 = (const float*)d_in[dictOrder ? 1 : 3];
    const float* K1 = (const float*)d_in[dictOrder ? 2 : 1];
    const float* V1 = (const float*)d_in[dictOrder ? 3 : 4];
    const float* K2 = (const float*)d_in[dictOrder ? 4 : 2];
    const float* V2 = (const float*)d_in[5];
    const float* Q0 = (const float*)d_in[6];
    const float* Q1 = (const float*)d_in[7];
    const float* LNG  = (const float*)d_in[8];
    const float* LNB  = (const float*)d_in[9];
    const float* KW1  = (const float*)d_in[10];
    const float* KB1  = (const float*)d_in[11];
    const float* KW2  = (const float*)d_in[12];
    const float* KB2  = (const float*)d_in[13];
    const float* QW1  = (const float*)d_in[14];
    const float* QB1  = (const float*)d_in[15];
    const float* QW2  = (const float*)d_in[16];
    const float* QB2  = (const float*)d_in[17];
    const float* WEXP = (const float*)d_in[18];
    const float* BEXP = (const float*)d_in[19];
    const float* WDW  = (const float*)d_in[20];
    const float* BDW  = (const float*)d_in[21];
    const float* WPRJ = (const float*)d_in[22];
    const float* BPRJ = (const float*)d_in[23];
    float* out = (float*)d_out;

    float *kseq, *vseq, *qseq, *khid, *kemb, *qhid, *qemb, *x0, *x1, *hid1, *hid2, *wtd;
    GETSYM(kseq, g_kseq); GETSYM(vseq, g_vseq); GETSYM(qseq, g_qseq);
    GETSYM(khid, g_khid); GETSYM(kemb, g_kemb);
    GETSYM(qhid, g_qhid); GETSYM(qemb, g_qemb);
    GETSYM(x0, g_x0); GETSYM(x1, g_x1);
    GETSYM(hid1, g_hid1); GETSYM(hid2, g_hid2);
    GETSYM(wtd, g_weighted);

    // 1) patchify
    k_patchify<<<2097152/256,256>>>(K0, kseq, 16,256,256,    0, NKTOT, KPD, 2097152);
    k_patchify<<<1966080/256,256>>>(K1, kseq, 16,192,320, 1024, NKTOT, KPD, 1966080);
    k_patchify<<< 524288/256,256>>>(K2, kseq, 16,128,128, 1984, NKTOT, KPD,  524288);
    k_patchify<<<4194304/256,256>>>(V0, vseq, 32,256,256,    0, NKTOT, VPD, 4194304);
    k_patchify<<<3932160/256,256>>>(V1, vseq, 32,192,320, 1024, NKTOT, VPD, 3932160);
    k_patchify<<<1048576/256,256>>>(V2, vseq, 32,128,128, 1984, NKTOT, VPD, 1048576);
    k_patchify<<<2097152/256,256>>>(Q0, qseq, 16,256,256,    0, NQTOT, QPD, 2097152);
    k_patchify<<<1179648/256,256>>>(Q1, qseq, 16,192,192, 1024, NQTOT, QPD, 1179648);

    // 2) layernorm values
    k_layernorm<<<BB*NKTOT,256>>>(vseq, LNG, LNB, VPD);

    // 3) embeddings (gelu MLP)
    k_gemm<<<dim3(ADIM/64, BB*NKTOT/64),256>>>(kseq, KPD, KW1, ADIM, KB1, khid, ADIM, KPD, 1);
    k_gemm<<<dim3(ADIM/64, BB*NKTOT/64),256>>>(khid, ADIM, KW2, ADIM, KB2, kemb, ADIM, ADIM, 0);
    k_gemm<<<dim3(ADIM/64, BB*NQTOT/64),256>>>(qseq, QPD, QW1, ADIM, QB1, qhid, ADIM, QPD, 1);
    k_gemm<<<dim3(ADIM/64, BB*NQTOT/64),256>>>(qhid, ADIM, QW2, ADIM, QB2, qemb, ADIM, ADIM, 0);

    // 4) attention
    k_qk<<<dim3(NKTOT/64, NQTOT/64, BB*HEADS),256>>>();
    k_softmax<<<BB*HEADS*NQTOT,256>>>();
    k_av<<<dim3(VHD/64, NQTOT/64, BB*3*HEADS),256>>>();

    // 5) assemble conv inputs
    k_assemble<<<12582912/256,256>>>(wtd, x0, 256,256,    0, 12582912);
    k_assemble<<< 7077888/256,256>>>(wtd, x1, 192,192, 1024,  7077888);

    // 6) mbconv image 0 (256x256)
    {
        int npix = 256*256;
        k_expand<<<dim3(npix/32, BB),256>>>(x0, WEXP, BEXP, hid1, npix);
        k_dw<<<dim3(256/32, 256/8, BB*384), dim3(32,8)>>>(hid1, WDW, BDW, hid2, 256, 256);
        k_proj<<<dim3(npix/32, BB),256>>>(hid2, WPRJ, BPRJ, out, npix);
    }
    // 7) mbconv image 1 (192x192)
    {
        int npix = 192*192;
        k_expand<<<dim3(npix/32, BB),256>>>(x1, WEXP, BEXP, hid1, npix);
        k_dw<<<dim3(192/32, 192/8, BB*384), dim3(32,8)>>>(hid1, WDW, BDW, hid2, 192, 192);
        k_proj<<<dim3(npix/32, BB),256>>>(hid2, WPRJ, BPRJ, out + (size_t)BB*32*256*256, npix);
    }
}